// round 11
// baseline (speedup 1.0000x reference)
#include <cuda_runtime.h>
#include <cuda_fp16.h>
#include <cstdint>

#define NN 50000
#define NE 1600000
#define DIN 256
#define DH 128
#define DO 40

#define SCAN_BLK 512
#define SCAN_NB ((NN + SCAN_BLK - 1) / SCAN_BLK)   // 98

#define GEMM1_BLOCKS ((NN + 127) / 128)            // 391
#define EDGE_BLOCKS ((NE / 4 + 255) / 256)         // 1563

// -------- scratch (static device globals; no allocation allowed) --------
// NOTE: g_deg is self-cleaning — k_scan zeroes it after reading, so each
// graph replay sees zeroed counters (first execution relies on zero BSS).
static __device__ __align__(16) __half g_h1h[(size_t)NN * DH];   // x@W1 (fp16, gather source)
static __device__ __align__(16) __half g_a1h[(size_t)NN * DH];   // relu(agg1+b1) (fp16)
static __device__ __align__(16) __half g_h2h[(size_t)NN * DO];   // layer2 pre-agg (fp16)
static __device__ int      g_deg[NN];
static __device__ float    g_dinv[NN];
static __device__ int      g_off[NN];
static __device__ int      g_pos[NN];    // after scatter: row end (off+deg)
static __device__ unsigned g_edge[NE];   // packed: (src << 16) | fp16(coef)
static __device__ int      g_total;      // scan ticket (self-resetting)
static __device__ int      g_done;       // scan completion counter (self-resetting)

// -------- per-block edge dtype detection (odd 32-bit words all zero <=> int64) --------
__device__ __forceinline__ bool detect_is64(const int* __restrict__ ei32, int tid, int nthr) {
    __shared__ int s64;
    if (tid == 0) s64 = 1;
    __syncthreads();
    int any = 0;
    for (int i = tid; i < 2048; i += nthr) any |= ei32[2 * i + 1];
    if (any) s64 = 0;
    __syncthreads();
    return s64 != 0;
}

// -------- degree histogram: local detect + 4 edges/thread --------
__global__ void __launch_bounds__(256) k_deg(const void* __restrict__ ei) {
    bool is64 = detect_is64((const int*)ei, threadIdx.x, 256);
    int t = blockIdx.x * blockDim.x + threadIdx.x;
    if (!is64) {
        if (t < NE / 4) {
            int4 d4 = ((const int4*)((const int*)ei + NE))[t];
            if ((unsigned)d4.x < NN) atomicAdd(&g_deg[d4.x], 1);
            if ((unsigned)d4.y < NN) atomicAdd(&g_deg[d4.y], 1);
            if ((unsigned)d4.z < NN) atomicAdd(&g_deg[d4.z], 1);
            if ((unsigned)d4.w < NN) atomicAdd(&g_deg[d4.w], 1);
        }
    } else {
        for (int e = t * 4; e < t * 4 + 4 && e < NE; e++) {
            int d = (int)((const long long*)ei)[NE + e];
            if ((unsigned)d < NN) atomicAdd(&g_deg[d], 1);
        }
    }
}

// -------- single-kernel ticket scan + dinv; zeroes g_deg for next replay --------
__global__ void k_scan() {
    __shared__ int sh[SCAN_BLK];
    __shared__ int base;
    int t = threadIdx.x;
    int i = blockIdx.x * SCAN_BLK + t;
    int v = (i < NN) ? g_deg[i] : 0;
    if (i < NN) g_deg[i] = 0;        // self-clean (only this thread reads g_deg[i])
    sh[t] = v;
    __syncthreads();
#pragma unroll
    for (int o = 1; o < SCAN_BLK; o <<= 1) {
        int x = (t >= o) ? sh[t - o] : 0;
        __syncthreads();
        sh[t] += x;
        __syncthreads();
    }
    if (t == SCAN_BLK - 1) base = atomicAdd(&g_total, sh[t]);
    __syncthreads();
    if (i < NN) {
        int off = base + sh[t] - v;  // exclusive within arrival-ordered layout
        g_off[i] = off;
        g_pos[i] = off;
        g_dinv[i] = rsqrtf((float)(v + 1));
    }
    __threadfence();
    if (t == 0) {
        if (atomicAdd(&g_done, 1) == gridDim.x - 1) {
            g_total = 0;
            g_done = 0;
        }
    }
}

// -------- async copy helpers --------
__device__ __forceinline__ void cp_async16(void* smem, const void* gmem, bool pred) {
    uint32_t sa = (uint32_t)__cvta_generic_to_shared(smem);
    int sz = pred ? 16 : 0;
    asm volatile("cp.async.cg.shared.global [%0], [%1], 16, %2;" :: "r"(sa), "l"(gmem), "r"(sz));
}
__device__ __forceinline__ void cp_commit() { asm volatile("cp.async.commit_group;"); }
template <int N>
__device__ __forceinline__ void cp_wait() { asm volatile("cp.async.wait_group %0;" :: "n"(N)); }

__device__ __forceinline__ void mma_tf32(float& d0, float& d1, float& d2, float& d3,
                                         uint32_t a0, uint32_t a1, uint32_t a2, uint32_t a3,
                                         uint32_t b0, uint32_t b1) {
    asm volatile(
        "mma.sync.aligned.m16n8k8.row.col.f32.tf32.tf32.f32 "
        "{%0,%1,%2,%3}, {%4,%5,%6,%7}, {%8,%9}, {%0,%1,%2,%3};"
        : "+f"(d0), "+f"(d1), "+f"(d2), "+f"(d3)
        : "r"(a0), "r"(a1), "r"(a2), "r"(a3), "r"(b0), "r"(b1));
}

// ======== COMBINED LAUNCH: blocks [0,391) = GEMM1, blocks [391,...) = scatter ========
#define LDA 20
#define LDB 136
#define NT (DIN / 16)   // 16 k-tiles

__device__ void gemm1_body(const float* __restrict__ X, const float* __restrict__ W,
                           int bid) {
    __shared__ __align__(16) uint32_t Ah[2][128 * LDA];
    __shared__ __align__(16) uint32_t Bh[2][16 * LDB];

    int tid = threadIdx.x;
    int lane = tid & 31;
    int wid = tid >> 5;
    int wm = wid & 3;
    int wn = wid >> 2;
    int g = lane >> 2;
    int t = lane & 3;
    int r0 = bid * 128;

    int arow = tid >> 2, ac4 = tid & 3;
    int brow = tid >> 5, bc4 = tid & 31;

    auto load_tile = [&](int it, int buf) {
#pragma unroll
        for (int q = 0; q < 2; q++) {
            int row = arow + q * 64;
            cp_async16(&Ah[buf][row * LDA + ac4 * 4],
                       X + (size_t)(r0 + row) * DIN + it * 16 + ac4 * 4,
                       r0 + row < NN);
        }
#pragma unroll
        for (int q = 0; q < 2; q++) {
            int kr = brow + q * 8;
            cp_async16(&Bh[buf][kr * LDB + bc4 * 4],
                       W + (size_t)(it * 16 + kr) * DH + bc4 * 4, true);
        }
    };

    float acc[2][8][4];
#pragma unroll
    for (int i = 0; i < 2; i++)
#pragma unroll
        for (int j = 0; j < 8; j++)
#pragma unroll
            for (int k = 0; k < 4; k++) acc[i][j][k] = 0.f;

    load_tile(0, 0);
    cp_commit();

    for (int it = 0; it < NT; it++) {
        int buf = it & 1;
        if (it + 1 < NT) {
            load_tile(it + 1, (it + 1) & 1);
            cp_commit();
            cp_wait<1>();
        } else {
            cp_wait<0>();
        }
        __syncthreads();

#pragma unroll
        for (int kk = 0; kk < 2; kk++) {
            int kb = kk * 8;
            uint32_t ah[2][4];
#pragma unroll
            for (int mt = 0; mt < 2; mt++) {
                int rbase = (wm * 32 + mt * 16) * LDA + kb + t;
                ah[mt][0] = Ah[buf][rbase + g * LDA];
                ah[mt][1] = Ah[buf][rbase + (g + 8) * LDA];
                ah[mt][2] = Ah[buf][rbase + g * LDA + 4];
                ah[mt][3] = Ah[buf][rbase + (g + 8) * LDA + 4];
            }
            uint32_t bh[8][2];
#pragma unroll
            for (int nt = 0; nt < 8; nt++) {
                int cbase = wn * 64 + nt * 8 + g;
                bh[nt][0] = Bh[buf][(kb + t) * LDB + cbase];
                bh[nt][1] = Bh[buf][(kb + t + 4) * LDB + cbase];
            }
#pragma unroll
            for (int mt = 0; mt < 2; mt++)
#pragma unroll
                for (int nt = 0; nt < 8; nt++) {
                    float* d = acc[mt][nt];
                    mma_tf32(d[0], d[1], d[2], d[3],
                             ah[mt][0], ah[mt][1], ah[mt][2], ah[mt][3],
                             bh[nt][0], bh[nt][1]);
                }
        }
        __syncthreads();
    }

#pragma unroll
    for (int mt = 0; mt < 2; mt++) {
#pragma unroll
        for (int nt = 0; nt < 8; nt++) {
            int col = wn * 64 + nt * 8 + 2 * t;
            int rowa = r0 + wm * 32 + mt * 16 + g;
            int rowb = rowa + 8;
            float* d = acc[mt][nt];
            if (rowa < NN)
                *(__half2*)(g_h1h + (size_t)rowa * DH + col) = __floats2half2_rn(d[0], d[1]);
            if (rowb < NN)
                *(__half2*)(g_h1h + (size_t)rowb * DH + col) = __floats2half2_rn(d[2], d[3]);
        }
    }
}

__device__ void scatter_body(const void* __restrict__ ei, int bid, bool is64) {
    int t = bid * 256 + threadIdx.x;
    if (!is64) {
        if (t < NE / 4) {
            int4 s4 = ((const int4*)ei)[t];
            int4 d4 = ((const int4*)((const int*)ei + NE))[t];
            int ss[4] = {s4.x, s4.y, s4.z, s4.w};
            int dd[4] = {d4.x, d4.y, d4.z, d4.w};
#pragma unroll
            for (int q = 0; q < 4; q++) {
                int s = ss[q], d = dd[q];
                if ((unsigned)s < NN && (unsigned)d < NN) {
                    int slot = atomicAdd(&g_pos[d], 1);
                    unsigned hb = __half_as_ushort(__float2half_rn(g_dinv[s] * g_dinv[d]));
                    g_edge[slot] = ((unsigned)s << 16) | hb;
                }
            }
        }
    } else {
        for (int e = t * 4; e < t * 4 + 4 && e < NE; e++) {
            int s = (int)((const long long*)ei)[e];
            int d = (int)((const long long*)ei)[NE + e];
            if ((unsigned)s < NN && (unsigned)d < NN) {
                int slot = atomicAdd(&g_pos[d], 1);
                unsigned hb = __half_as_ushort(__float2half_rn(g_dinv[s] * g_dinv[d]));
                g_edge[slot] = ((unsigned)s << 16) | hb;
            }
        }
    }
}

__global__ void __launch_bounds__(256)
k_gemm1_scatter(const float* __restrict__ X, const float* __restrict__ W,
                const void* __restrict__ ei) {
    if (blockIdx.x < GEMM1_BLOCKS) {
        gemm1_body(X, W, blockIdx.x);
    } else {
        bool is64 = detect_is64((const int*)ei, threadIdx.x, 256);
        scatter_body(ei, blockIdx.x - GEMM1_BLOCKS, is64);
    }
}

// -------- layer1 aggregation: warp per node, half-warp per edge, uint4 gather --------
__global__ void k_agg1(const float* __restrict__ B1) {
    int t = blockIdx.x * blockDim.x + threadIdx.x;
    int w = t >> 5, lane = t & 31;
    if (w >= NN) return;
    int half = lane >> 4;
    int l = lane & 15;
    const uint4* __restrict__ H4 = (const uint4*)g_h1h;   // row = 16 uint4
    float acc[8];
#pragma unroll
    for (int i = 0; i < 8; i++) acc[i] = 0.f;

    float dv = g_dinv[w];
    if (half == 0) {
        float c0 = dv * dv;
        uint4 u = H4[(size_t)w * 16 + l];
        float2 f0 = __half22float2(*(__half2*)&u.x);
        float2 f1 = __half22float2(*(__half2*)&u.y);
        float2 f2 = __half22float2(*(__half2*)&u.z);
        float2 f3 = __half22float2(*(__half2*)&u.w);
        acc[0] = c0 * f0.x; acc[1] = c0 * f0.y; acc[2] = c0 * f1.x; acc[3] = c0 * f1.y;
        acc[4] = c0 * f2.x; acc[5] = c0 * f2.y; acc[6] = c0 * f3.x; acc[7] = c0 * f3.y;
    }

    int j = g_off[w];
    int end = g_pos[w];   // after scatter: off + deg
    for (; j + 4 <= end; j += 4) {
        unsigned ea = g_edge[j + half];
        unsigned eb = g_edge[j + 2 + half];
        uint4 ua = H4[(size_t)(ea >> 16) * 16 + l];
        uint4 ub = H4[(size_t)(eb >> 16) * 16 + l];
        float ca = __half2float(__ushort_as_half((unsigned short)(ea & 0xffffu)));
        float cb = __half2float(__ushort_as_half((unsigned short)(eb & 0xffffu)));
        {
            float2 f0 = __half22float2(*(__half2*)&ua.x);
            float2 f1 = __half22float2(*(__half2*)&ua.y);
            float2 f2 = __half22float2(*(__half2*)&ua.z);
            float2 f3 = __half22float2(*(__half2*)&ua.w);
            acc[0] += ca * f0.x; acc[1] += ca * f0.y; acc[2] += ca * f1.x; acc[3] += ca * f1.y;
            acc[4] += ca * f2.x; acc[5] += ca * f2.y; acc[6] += ca * f3.x; acc[7] += ca * f3.y;
        }
        {
            float2 f0 = __half22float2(*(__half2*)&ub.x);
            float2 f1 = __half22float2(*(__half2*)&ub.y);
            float2 f2 = __half22float2(*(__half2*)&ub.z);
            float2 f3 = __half22float2(*(__half2*)&ub.w);
            acc[0] += cb * f0.x; acc[1] += cb * f0.y; acc[2] += cb * f1.x; acc[3] += cb * f1.y;
            acc[4] += cb * f2.x; acc[5] += cb * f2.y; acc[6] += cb * f3.x; acc[7] += cb * f3.y;
        }
    }
    if (j + 2 <= end) {
        unsigned ea = g_edge[j + half];
        uint4 ua = H4[(size_t)(ea >> 16) * 16 + l];
        float ca = __half2float(__ushort_as_half((unsigned short)(ea & 0xffffu)));
        float2 f0 = __half22float2(*(__half2*)&ua.x);
        float2 f1 = __half22float2(*(__half2*)&ua.y);
        float2 f2 = __half22float2(*(__half2*)&ua.z);
        float2 f3 = __half22float2(*(__half2*)&ua.w);
        acc[0] += ca * f0.x; acc[1] += ca * f0.y; acc[2] += ca * f1.x; acc[3] += ca * f1.y;
        acc[4] += ca * f2.x; acc[5] += ca * f2.y; acc[6] += ca * f3.x; acc[7] += ca * f3.y;
        j += 2;
    }
    if (j < end && half == 0) {
        unsigned ea = g_edge[j];
        uint4 ua = H4[(size_t)(ea >> 16) * 16 + l];
        float ca = __half2float(__ushort_as_half((unsigned short)(ea & 0xffffu)));
        float2 f0 = __half22float2(*(__half2*)&ua.x);
        float2 f1 = __half22float2(*(__half2*)&ua.y);
        float2 f2 = __half22float2(*(__half2*)&ua.z);
        float2 f3 = __half22float2(*(__half2*)&ua.w);
        acc[0] += ca * f0.x; acc[1] += ca * f0.y; acc[2] += ca * f1.x; acc[3] += ca * f1.y;
        acc[4] += ca * f2.x; acc[5] += ca * f2.y; acc[6] += ca * f3.x; acc[7] += ca * f3.y;
    }

#pragma unroll
    for (int i = 0; i < 8; i++) acc[i] += __shfl_xor_sync(0xffffffffu, acc[i], 16);

    if (half == 0) {
        float4 b0 = ((const float4*)B1)[2 * l];
        float4 b1v = ((const float4*)B1)[2 * l + 1];
        acc[0] = fmaxf(acc[0] + b0.x, 0.f); acc[1] = fmaxf(acc[1] + b0.y, 0.f);
        acc[2] = fmaxf(acc[2] + b0.z, 0.f); acc[3] = fmaxf(acc[3] + b0.w, 0.f);
        acc[4] = fmaxf(acc[4] + b1v.x, 0.f); acc[5] = fmaxf(acc[5] + b1v.y, 0.f);
        acc[6] = fmaxf(acc[6] + b1v.z, 0.f); acc[7] = fmaxf(acc[7] + b1v.w, 0.f);
        __half2 h0 = __floats2half2_rn(acc[0], acc[1]);
        __half2 h1 = __floats2half2_rn(acc[2], acc[3]);
        __half2 h2 = __floats2half2_rn(acc[4], acc[5]);
        __half2 h3 = __floats2half2_rn(acc[6], acc[7]);
        uint4 st;
        st.x = *(unsigned*)&h0; st.y = *(unsigned*)&h1;
        st.z = *(unsigned*)&h2; st.w = *(unsigned*)&h3;
        ((uint4*)g_a1h)[(size_t)w * 16 + l] = st;
    }
}

// -------- GEMM2: h2h[NN,40] = a1h[NN,128] @ W2[128,40] --------
__global__ void k_gemm2(const float* __restrict__ W2) {
    __shared__ __align__(16) float As[128][65];
    __shared__ float Bs[64][40];
    int tid = threadIdx.x;
    int r0 = blockIdx.x * 128;
    int tx = tid & 7;
    int ty = tid >> 3;
    float acc[4][5];
#pragma unroll
    for (int i = 0; i < 4; i++)
#pragma unroll
        for (int c = 0; c < 5; c++) acc[i][c] = 0.f;

    for (int kt = 0; kt < DH; kt += 64) {
#pragma unroll
        for (int q = 0; q < 8; q++) {
            int id = tid + q * 256;
            int row = id >> 4, c4 = id & 15;
            float4 v = make_float4(0.f, 0.f, 0.f, 0.f);
            if (r0 + row < NN) {
                uint2 u = *(const uint2*)(g_a1h + (size_t)(r0 + row) * DH + kt + c4 * 4);
                float2 f0 = __half22float2(*(__half2*)&u.x);
                float2 f1 = __half22float2(*(__half2*)&u.y);
                v = make_float4(f0.x, f0.y, f1.x, f1.y);
            }
            As[row][c4 * 4 + 0] = v.x; As[row][c4 * 4 + 1] = v.y;
            As[row][c4 * 4 + 2] = v.z; As[row][c4 * 4 + 3] = v.w;
        }
#pragma unroll
        for (int q = 0; q < 10; q++) {
            int id = tid + q * 256;
            int k = id / 40, c = id % 40;
            Bs[k][c] = W2[(size_t)(kt + k) * DO + c];
        }
        __syncthreads();
#pragma unroll 8
        for (int k = 0; k < 64; k++) {
            float b[5];
#pragma unroll
            for (int c = 0; c < 5; c++) b[c] = Bs[k][tx * 5 + c];
#pragma unroll
            for (int i = 0; i < 4; i++) {
                float a = As[ty * 4 + i][k];
#pragma unroll
                for (int c = 0; c < 5; c++) acc[i][c] += a * b[c];
            }
        }
        __syncthreads();
    }
#pragma unroll
    for (int i = 0; i < 4; i++) {
        int row = r0 + ty * 4 + i;
        if (row < NN) {
#pragma unroll
            for (int c = 0; c < 5; c++)
                g_h2h[(size_t)row * DO + tx * 5 + c] = __float2half_rn(acc[i][c]);
        }
    }
}

// -------- layer2 aggregation + bias + log_softmax fused, 4x unroll --------
__global__ void k_agg2_logsm(float* __restrict__ out, const float* __restrict__ B2) {
    int t = blockIdx.x * blockDim.x + threadIdx.x;
    int w = t >> 5, lane = t & 31;
    if (w >= NN) return;
    bool act = lane < 20;
    float dv = g_dinv[w];
    float c0 = dv * dv;
    const __half2* __restrict__ Hh = (const __half2*)g_h2h;
    float acc0 = 0.f, acc1 = 0.f;
    if (act) {
        float2 f = __half22float2(Hh[(size_t)w * 20 + lane]);
        acc0 = c0 * f.x;
        acc1 = c0 * f.y;
    }
    int j = g_off[w];
    int end = g_pos[w];
    int lidx = act ? lane : 0;
    for (; j + 4 <= end; j += 4) {
        unsigned ew[4];
#pragma unroll
        for (int q = 0; q < 4; q++) ew[q] = g_edge[j + q];
        __half2 u[4];
#pragma unroll
        for (int q = 0; q < 4; q++) u[q] = Hh[(size_t)(ew[q] >> 16) * 20 + lidx];
        if (act) {
#pragma unroll
            for (int q = 0; q < 4; q++) {
                float c = __half2float(__ushort_as_half((unsigned short)(ew[q] & 0xffffu)));
                float2 f = __half22float2(u[q]);
                acc0 += c * f.x;
                acc1 += c * f.y;
            }
        }
    }
    for (; j < end; j++) {
        unsigned e0 = g_edge[j];
        float2 f = __half22float2(Hh[(size_t)(e0 >> 16) * 20 + lidx]);
        if (act) {
            float c = __half2float(__ushort_as_half((unsigned short)(e0 & 0xffffu)));
            acc0 += c * f.x;
            acc1 += c * f.y;
        }
    }
    if (act) {
        acc0 += B2[2 * lane];
        acc1 += B2[2 * lane + 1];
    }
    float m = act ? fmaxf(acc0, acc1) : __int_as_float(0xff800000);
#pragma unroll
    for (int o = 16; o > 0; o >>= 1) m = fmaxf(m, __shfl_xor_sync(0xffffffffu, m, o));
    float s = act ? (expf(acc0 - m) + expf(acc1 - m)) : 0.f;
#pragma unroll
    for (int o = 16; o > 0; o >>= 1) s += __shfl_xor_sync(0xffffffffu, s, o);
    float lse = m + logf(s);
    if (act)
        *(float2*)(out + (size_t)w * DO + 2 * lane) = make_float2(acc0 - lse, acc1 - lse);
}

// -------- launch --------
extern "C" void kernel_launch(void* const* d_in, const int* in_sizes, int n_in,
                              void* d_out, int out_size) {
    const float* x  = (const float*)d_in[0];
    const void*  ei = d_in[1];
    const float* W1 = (const float*)d_in[2];
    const float* b1 = (const float*)d_in[3];
    const float* W2 = (const float*)d_in[4];
    const float* b2 = (const float*)d_in[5];
    float* out = (float*)d_out;

    (void)in_sizes; (void)n_in; (void)out_size;

    k_deg<<<EDGE_BLOCKS, 256>>>(ei);                                       // 0
    k_scan<<<SCAN_NB, SCAN_BLK>>>();                                       // 1
    k_gemm1_scatter<<<GEMM1_BLOCKS + EDGE_BLOCKS, 256>>>(x, W1, ei);       // 2 (overlapped)
    k_agg1<<<(int)(((size_t)NN * 32 + 255) / 256), 256>>>(b1);             // 3  <- ncu capture slot
    k_gemm2<<<(NN + 127) / 128, 256>>>(W2);                                // 4
    k_agg2_logsm<<<(int)(((size_t)NN * 32 + 255) / 256), 256>>>(out, b2);  // 5
}

// round 12
// speedup vs baseline: 1.0311x; 1.0311x over previous
#include <cuda_runtime.h>
#include <cuda_fp16.h>
#include <cstdint>

#define NN 50000
#define NE 1600000
#define DIN 256
#define DH 128
#define DO 40

#define SCAN_BLK 512
#define SCAN_NB ((NN + SCAN_BLK - 1) / SCAN_BLK)   // 98

#define GEMM1_BLOCKS ((NN + 127) / 128)            // 391
#define EDGE_BLOCKS ((NE / 4 + 255) / 256)         // 1563

// -------- scratch (static device globals; no allocation allowed) --------
// g_deg is self-cleaning: k_scan zeroes it after reading (first run uses zero BSS).
static __device__ __align__(16) __half g_h1h[(size_t)NN * DH];   // x@W1 (fp16)
static __device__ __align__(16) __half g_a1h[(size_t)NN * DH];   // relu(agg1+b1) (fp16)
static __device__ __align__(16) __half g_h2h[(size_t)NN * DO];   // layer2 pre-agg (fp16)
static __device__ int      g_deg[NN];
static __device__ float    g_dinv[NN];
static __device__ int      g_off[NN];     // CSR row start
static __device__ int      g_pos[NN];     // CSR row end (off + deg), set by scan
static __device__ int      g_rank[NE];    // per-edge rank within its dst bucket
static __device__ unsigned g_edge[NE];    // packed: (src << 16) | fp16(coef)
static __device__ int      g_total;       // scan ticket (self-resetting)
static __device__ int      g_done;        // scan completion counter (self-resetting)

// -------- per-block edge dtype detection (odd 32-bit words all zero <=> int64) --------
__device__ __forceinline__ bool detect_is64(const int* __restrict__ ei32, int tid, int nthr) {
    __shared__ int s64;
    if (tid == 0) s64 = 1;
    __syncthreads();
    int any = 0;
    for (int i = tid; i < 2048; i += nthr) any |= ei32[2 * i + 1];
    if (any) s64 = 0;
    __syncthreads();
    return s64 != 0;
}

// -------- async copy helpers --------
__device__ __forceinline__ void cp_async16(void* smem, const void* gmem, bool pred) {
    uint32_t sa = (uint32_t)__cvta_generic_to_shared(smem);
    int sz = pred ? 16 : 0;
    asm volatile("cp.async.cg.shared.global [%0], [%1], 16, %2;" :: "r"(sa), "l"(gmem), "r"(sz));
}
__device__ __forceinline__ void cp_commit() { asm volatile("cp.async.commit_group;"); }
template <int N>
__device__ __forceinline__ void cp_wait() { asm volatile("cp.async.wait_group %0;" :: "n"(N)); }

__device__ __forceinline__ void mma_tf32(float& d0, float& d1, float& d2, float& d3,
                                         uint32_t a0, uint32_t a1, uint32_t a2, uint32_t a3,
                                         uint32_t b0, uint32_t b1) {
    asm volatile(
        "mma.sync.aligned.m16n8k8.row.col.f32.tf32.tf32.f32 "
        "{%0,%1,%2,%3}, {%4,%5,%6,%7}, {%8,%9}, {%0,%1,%2,%3};"
        : "+f"(d0), "+f"(d1), "+f"(d2), "+f"(d3)
        : "r"(a0), "r"(a1), "r"(a2), "r"(a3), "r"(b0), "r"(b1));
}

// ======== COMBINED LAUNCH: blocks [0,391) = GEMM1, blocks [391,...) = degree+rank ========
#define LDA 20
#define LDB 136
#define NT (DIN / 16)   // 16 k-tiles

__device__ void gemm1_body(const float* __restrict__ X, const float* __restrict__ W,
                           int bid) {
    __shared__ __align__(16) uint32_t Ah[2][128 * LDA];
    __shared__ __align__(16) uint32_t Bh[2][16 * LDB];

    int tid = threadIdx.x;
    int lane = tid & 31;
    int wid = tid >> 5;
    int wm = wid & 3;
    int wn = wid >> 2;
    int g = lane >> 2;
    int t = lane & 3;
    int r0 = bid * 128;

    int arow = tid >> 2, ac4 = tid & 3;
    int brow = tid >> 5, bc4 = tid & 31;

    auto load_tile = [&](int it, int buf) {
#pragma unroll
        for (int q = 0; q < 2; q++) {
            int row = arow + q * 64;
            cp_async16(&Ah[buf][row * LDA + ac4 * 4],
                       X + (size_t)(r0 + row) * DIN + it * 16 + ac4 * 4,
                       r0 + row < NN);
        }
#pragma unroll
        for (int q = 0; q < 2; q++) {
            int kr = brow + q * 8;
            cp_async16(&Bh[buf][kr * LDB + bc4 * 4],
                       W + (size_t)(it * 16 + kr) * DH + bc4 * 4, true);
        }
    };

    float acc[2][8][4];
#pragma unroll
    for (int i = 0; i < 2; i++)
#pragma unroll
        for (int j = 0; j < 8; j++)
#pragma unroll
            for (int k = 0; k < 4; k++) acc[i][j][k] = 0.f;

    load_tile(0, 0);
    cp_commit();

    for (int it = 0; it < NT; it++) {
        int buf = it & 1;
        if (it + 1 < NT) {
            load_tile(it + 1, (it + 1) & 1);
            cp_commit();
            cp_wait<1>();
        } else {
            cp_wait<0>();
        }
        __syncthreads();

#pragma unroll
        for (int kk = 0; kk < 2; kk++) {
            int kb = kk * 8;
            uint32_t ah[2][4];
#pragma unroll
            for (int mt = 0; mt < 2; mt++) {
                int rbase = (wm * 32 + mt * 16) * LDA + kb + t;
                ah[mt][0] = Ah[buf][rbase + g * LDA];
                ah[mt][1] = Ah[buf][rbase + (g + 8) * LDA];
                ah[mt][2] = Ah[buf][rbase + g * LDA + 4];
                ah[mt][3] = Ah[buf][rbase + (g + 8) * LDA + 4];
            }
            uint32_t bh[8][2];
#pragma unroll
            for (int nt = 0; nt < 8; nt++) {
                int cbase = wn * 64 + nt * 8 + g;
                bh[nt][0] = Bh[buf][(kb + t) * LDB + cbase];
                bh[nt][1] = Bh[buf][(kb + t + 4) * LDB + cbase];
            }
#pragma unroll
            for (int mt = 0; mt < 2; mt++)
#pragma unroll
                for (int nt = 0; nt < 8; nt++) {
                    float* d = acc[mt][nt];
                    mma_tf32(d[0], d[1], d[2], d[3],
                             ah[mt][0], ah[mt][1], ah[mt][2], ah[mt][3],
                             bh[nt][0], bh[nt][1]);
                }
        }
        __syncthreads();
    }

#pragma unroll
    for (int mt = 0; mt < 2; mt++) {
#pragma unroll
        for (int nt = 0; nt < 8; nt++) {
            int col = wn * 64 + nt * 8 + 2 * t;
            int rowa = r0 + wm * 32 + mt * 16 + g;
            int rowb = rowa + 8;
            float* d = acc[mt][nt];
            if (rowa < NN)
                *(__half2*)(g_h1h + (size_t)rowa * DH + col) = __floats2half2_rn(d[0], d[1]);
            if (rowb < NN)
                *(__half2*)(g_h1h + (size_t)rowb * DH + col) = __floats2half2_rn(d[2], d[3]);
        }
    }
}

// degree + rank capture: the histogram atomic's return value IS the edge's rank
__device__ void deg_body(const void* __restrict__ ei, int bid, bool is64) {
    int t = bid * 256 + threadIdx.x;
    if (!is64) {
        if (t < NE / 4) {
            int4 d4 = ((const int4*)((const int*)ei + NE))[t];
            int dd[4] = {d4.x, d4.y, d4.z, d4.w};
            int rr[4] = {0, 0, 0, 0};
#pragma unroll
            for (int q = 0; q < 4; q++)
                if ((unsigned)dd[q] < NN) rr[q] = atomicAdd(&g_deg[dd[q]], 1);
            ((int4*)g_rank)[t] = make_int4(rr[0], rr[1], rr[2], rr[3]);
        }
    } else {
        for (int e = t * 4; e < t * 4 + 4 && e < NE; e++) {
            int d = (int)((const long long*)ei)[NE + e];
            int r = 0;
            if ((unsigned)d < NN) r = atomicAdd(&g_deg[d], 1);
            g_rank[e] = r;
        }
    }
}

__global__ void __launch_bounds__(256)
k_gemm1_deg(const float* __restrict__ X, const float* __restrict__ W,
            const void* __restrict__ ei) {
    if (blockIdx.x < GEMM1_BLOCKS) {
        gemm1_body(X, W, blockIdx.x);
    } else {
        bool is64 = detect_is64((const int*)ei, threadIdx.x, 256);
        deg_body(ei, blockIdx.x - GEMM1_BLOCKS, is64);
    }
}

// -------- ticket scan: g_off = row start, g_pos = row end, dinv; zero g_deg --------
__global__ void k_scan() {
    __shared__ int sh[SCAN_BLK];
    __shared__ int base;
    int t = threadIdx.x;
    int i = blockIdx.x * SCAN_BLK + t;
    int v = (i < NN) ? g_deg[i] : 0;
    if (i < NN) g_deg[i] = 0;        // self-clean (only this thread reads g_deg[i])
    sh[t] = v;
    __syncthreads();
#pragma unroll
    for (int o = 1; o < SCAN_BLK; o <<= 1) {
        int x = (t >= o) ? sh[t - o] : 0;
        __syncthreads();
        sh[t] += x;
        __syncthreads();
    }
    if (t == SCAN_BLK - 1) base = atomicAdd(&g_total, sh[t]);
    __syncthreads();
    if (i < NN) {
        int off = base + sh[t] - v;  // exclusive within arrival-ordered layout
        g_off[i] = off;
        g_pos[i] = off + v;          // row end
        g_dinv[i] = rsqrtf((float)(v + 1));
    }
    __threadfence();
    if (t == 0) {
        if (atomicAdd(&g_done, 1) == gridDim.x - 1) {
            g_total = 0;
            g_done = 0;
        }
    }
}

// -------- CSR fill, ATOMIC-FREE: slot = off[dst] + rank[e] --------
__global__ void __launch_bounds__(256) k_scatter(const void* __restrict__ ei) {
    bool is64 = detect_is64((const int*)ei, threadIdx.x, 256);
    int t = blockIdx.x * blockDim.x + threadIdx.x;
    if (!is64) {
        if (t < NE / 4) {
            int4 s4 = ((const int4*)ei)[t];
            int4 d4 = ((const int4*)((const int*)ei + NE))[t];
            int4 r4 = ((const int4*)g_rank)[t];
            int ss[4] = {s4.x, s4.y, s4.z, s4.w};
            int dd[4] = {d4.x, d4.y, d4.z, d4.w};
            int rr[4] = {r4.x, r4.y, r4.z, r4.w};
#pragma unroll
            for (int q = 0; q < 4; q++) {
                int s = ss[q], d = dd[q];
                if ((unsigned)s < NN && (unsigned)d < NN) {
                    int slot = g_off[d] + rr[q];
                    unsigned hb = __half_as_ushort(__float2half_rn(g_dinv[s] * g_dinv[d]));
                    g_edge[slot] = ((unsigned)s << 16) | hb;
                }
            }
        }
    } else {
        for (int e = t * 4; e < t * 4 + 4 && e < NE; e++) {
            int s = (int)((const long long*)ei)[e];
            int d = (int)((const long long*)ei)[NE + e];
            if ((unsigned)s < NN && (unsigned)d < NN) {
                int slot = g_off[d] + g_rank[e];
                unsigned hb = __half_as_ushort(__float2half_rn(g_dinv[s] * g_dinv[d]));
                g_edge[slot] = ((unsigned)s << 16) | hb;
            }
        }
    }
}

// -------- layer1 aggregation: warp per node, half-warp per edge, uint4 gather --------
__global__ void k_agg1(const float* __restrict__ B1) {
    int t = blockIdx.x * blockDim.x + threadIdx.x;
    int w = t >> 5, lane = t & 31;
    if (w >= NN) return;
    int half = lane >> 4;
    int l = lane & 15;
    const uint4* __restrict__ H4 = (const uint4*)g_h1h;   // row = 16 uint4
    float acc[8];
#pragma unroll
    for (int i = 0; i < 8; i++) acc[i] = 0.f;

    float dv = g_dinv[w];
    if (half == 0) {
        float c0 = dv * dv;
        uint4 u = H4[(size_t)w * 16 + l];
        float2 f0 = __half22float2(*(__half2*)&u.x);
        float2 f1 = __half22float2(*(__half2*)&u.y);
        float2 f2 = __half22float2(*(__half2*)&u.z);
        float2 f3 = __half22float2(*(__half2*)&u.w);
        acc[0] = c0 * f0.x; acc[1] = c0 * f0.y; acc[2] = c0 * f1.x; acc[3] = c0 * f1.y;
        acc[4] = c0 * f2.x; acc[5] = c0 * f2.y; acc[6] = c0 * f3.x; acc[7] = c0 * f3.y;
    }

    int j = g_off[w];
    int end = g_pos[w];
    for (; j + 4 <= end; j += 4) {
        unsigned ea = g_edge[j + half];
        unsigned eb = g_edge[j + 2 + half];
        uint4 ua = H4[(size_t)(ea >> 16) * 16 + l];
        uint4 ub = H4[(size_t)(eb >> 16) * 16 + l];
        float ca = __half2float(__ushort_as_half((unsigned short)(ea & 0xffffu)));
        float cb = __half2float(__ushort_as_half((unsigned short)(eb & 0xffffu)));
        {
            float2 f0 = __half22float2(*(__half2*)&ua.x);
            float2 f1 = __half22float2(*(__half2*)&ua.y);
            float2 f2 = __half22float2(*(__half2*)&ua.z);
            float2 f3 = __half22float2(*(__half2*)&ua.w);
            acc[0] += ca * f0.x; acc[1] += ca * f0.y; acc[2] += ca * f1.x; acc[3] += ca * f1.y;
            acc[4] += ca * f2.x; acc[5] += ca * f2.y; acc[6] += ca * f3.x; acc[7] += ca * f3.y;
        }
        {
            float2 f0 = __half22float2(*(__half2*)&ub.x);
            float2 f1 = __half22float2(*(__half2*)&ub.y);
            float2 f2 = __half22float2(*(__half2*)&ub.z);
            float2 f3 = __half22float2(*(__half2*)&ub.w);
            acc[0] += cb * f0.x; acc[1] += cb * f0.y; acc[2] += cb * f1.x; acc[3] += cb * f1.y;
            acc[4] += cb * f2.x; acc[5] += cb * f2.y; acc[6] += cb * f3.x; acc[7] += cb * f3.y;
        }
    }
    if (j + 2 <= end) {
        unsigned ea = g_edge[j + half];
        uint4 ua = H4[(size_t)(ea >> 16) * 16 + l];
        float ca = __half2float(__ushort_as_half((unsigned short)(ea & 0xffffu)));
        float2 f0 = __half22float2(*(__half2*)&ua.x);
        float2 f1 = __half22float2(*(__half2*)&ua.y);
        float2 f2 = __half22float2(*(__half2*)&ua.z);
        float2 f3 = __half22float2(*(__half2*)&ua.w);
        acc[0] += ca * f0.x; acc[1] += ca * f0.y; acc[2] += ca * f1.x; acc[3] += ca * f1.y;
        acc[4] += ca * f2.x; acc[5] += ca * f2.y; acc[6] += ca * f3.x; acc[7] += ca * f3.y;
        j += 2;
    }
    if (j < end && half == 0) {
        unsigned ea = g_edge[j];
        uint4 ua = H4[(size_t)(ea >> 16) * 16 + l];
        float ca = __half2float(__ushort_as_half((unsigned short)(ea & 0xffffu)));
        float2 f0 = __half22float2(*(__half2*)&ua.x);
        float2 f1 = __half22float2(*(__half2*)&ua.y);
        float2 f2 = __half22float2(*(__half2*)&ua.z);
        float2 f3 = __half22float2(*(__half2*)&ua.w);
        acc[0] += ca * f0.x; acc[1] += ca * f0.y; acc[2] += ca * f1.x; acc[3] += ca * f1.y;
        acc[4] += ca * f2.x; acc[5] += ca * f2.y; acc[6] += ca * f3.x; acc[7] += ca * f3.y;
    }

#pragma unroll
    for (int i = 0; i < 8; i++) acc[i] += __shfl_xor_sync(0xffffffffu, acc[i], 16);

    if (half == 0) {
        float4 b0 = ((const float4*)B1)[2 * l];
        float4 b1v = ((const float4*)B1)[2 * l + 1];
        acc[0] = fmaxf(acc[0] + b0.x, 0.f); acc[1] = fmaxf(acc[1] + b0.y, 0.f);
        acc[2] = fmaxf(acc[2] + b0.z, 0.f); acc[3] = fmaxf(acc[3] + b0.w, 0.f);
        acc[4] = fmaxf(acc[4] + b1v.x, 0.f); acc[5] = fmaxf(acc[5] + b1v.y, 0.f);
        acc[6] = fmaxf(acc[6] + b1v.z, 0.f); acc[7] = fmaxf(acc[7] + b1v.w, 0.f);
        __half2 h0 = __floats2half2_rn(acc[0], acc[1]);
        __half2 h1 = __floats2half2_rn(acc[2], acc[3]);
        __half2 h2 = __floats2half2_rn(acc[4], acc[5]);
        __half2 h3 = __floats2half2_rn(acc[6], acc[7]);
        uint4 st;
        st.x = *(unsigned*)&h0; st.y = *(unsigned*)&h1;
        st.z = *(unsigned*)&h2; st.w = *(unsigned*)&h3;
        ((uint4*)g_a1h)[(size_t)w * 16 + l] = st;
    }
}

// -------- GEMM2: h2h[NN,40] = a1h[NN,128] @ W2[128,40] --------
__global__ void k_gemm2(const float* __restrict__ W2) {
    __shared__ __align__(16) float As[128][65];
    __shared__ float Bs[64][40];
    int tid = threadIdx.x;
    int r0 = blockIdx.x * 128;
    int tx = tid & 7;
    int ty = tid >> 3;
    float acc[4][5];
#pragma unroll
    for (int i = 0; i < 4; i++)
#pragma unroll
        for (int c = 0; c < 5; c++) acc[i][c] = 0.f;

    for (int kt = 0; kt < DH; kt += 64) {
#pragma unroll
        for (int q = 0; q < 8; q++) {
            int id = tid + q * 256;
            int row = id >> 4, c4 = id & 15;
            float4 v = make_float4(0.f, 0.f, 0.f, 0.f);
            if (r0 + row < NN) {
                uint2 u = *(const uint2*)(g_a1h + (size_t)(r0 + row) * DH + kt + c4 * 4);
                float2 f0 = __half22float2(*(__half2*)&u.x);
                float2 f1 = __half22float2(*(__half2*)&u.y);
                v = make_float4(f0.x, f0.y, f1.x, f1.y);
            }
            As[row][c4 * 4 + 0] = v.x; As[row][c4 * 4 + 1] = v.y;
            As[row][c4 * 4 + 2] = v.z; As[row][c4 * 4 + 3] = v.w;
        }
#pragma unroll
        for (int q = 0; q < 10; q++) {
            int id = tid + q * 256;
            int k = id / 40, c = id % 40;
            Bs[k][c] = W2[(size_t)(kt + k) * DO + c];
        }
        __syncthreads();
#pragma unroll 8
        for (int k = 0; k < 64; k++) {
            float b[5];
#pragma unroll
            for (int c = 0; c < 5; c++) b[c] = Bs[k][tx * 5 + c];
#pragma unroll
            for (int i = 0; i < 4; i++) {
                float a = As[ty * 4 + i][k];
#pragma unroll
                for (int c = 0; c < 5; c++) acc[i][c] += a * b[c];
            }
        }
        __syncthreads();
    }
#pragma unroll
    for (int i = 0; i < 4; i++) {
        int row = r0 + ty * 4 + i;
        if (row < NN) {
#pragma unroll
            for (int c = 0; c < 5; c++)
                g_h2h[(size_t)row * DO + tx * 5 + c] = __float2half_rn(acc[i][c]);
        }
    }
}

// -------- layer2 aggregation + bias + log_softmax fused, 4x unroll --------
__global__ void k_agg2_logsm(float* __restrict__ out, const float* __restrict__ B2) {
    int t = blockIdx.x * blockDim.x + threadIdx.x;
    int w = t >> 5, lane = t & 31;
    if (w >= NN) return;
    bool act = lane < 20;
    float dv = g_dinv[w];
    float c0 = dv * dv;
    const __half2* __restrict__ Hh = (const __half2*)g_h2h;
    float acc0 = 0.f, acc1 = 0.f;
    if (act) {
        float2 f = __half22float2(Hh[(size_t)w * 20 + lane]);
        acc0 = c0 * f.x;
        acc1 = c0 * f.y;
    }
    int j = g_off[w];
    int end = g_pos[w];
    int lidx = act ? lane : 0;
    for (; j + 4 <= end; j += 4) {
        unsigned ew[4];
#pragma unroll
        for (int q = 0; q < 4; q++) ew[q] = g_edge[j + q];
        __half2 u[4];
#pragma unroll
        for (int q = 0; q < 4; q++) u[q] = Hh[(size_t)(ew[q] >> 16) * 20 + lidx];
        if (act) {
#pragma unroll
            for (int q = 0; q < 4; q++) {
                float c = __half2float(__ushort_as_half((unsigned short)(ew[q] & 0xffffu)));
                float2 f = __half22float2(u[q]);
                acc0 += c * f.x;
                acc1 += c * f.y;
            }
        }
    }
    for (; j < end; j++) {
        unsigned e0 = g_edge[j];
        float2 f = __half22float2(Hh[(size_t)(e0 >> 16) * 20 + lidx]);
        if (act) {
            float c = __half2float(__ushort_as_half((unsigned short)(e0 & 0xffffu)));
            acc0 += c * f.x;
            acc1 += c * f.y;
        }
    }
    if (act) {
        acc0 += B2[2 * lane];
        acc1 += B2[2 * lane + 1];
    }
    float m = act ? fmaxf(acc0, acc1) : __int_as_float(0xff800000);
#pragma unroll
    for (int o = 16; o > 0; o >>= 1) m = fmaxf(m, __shfl_xor_sync(0xffffffffu, m, o));
    float s = act ? (expf(acc0 - m) + expf(acc1 - m)) : 0.f;
#pragma unroll
    for (int o = 16; o > 0; o >>= 1) s += __shfl_xor_sync(0xffffffffu, s, o);
    float lse = m + logf(s);
    if (act)
        *(float2*)(out + (size_t)w * DO + 2 * lane) = make_float2(acc0 - lse, acc1 - lse);
}

// -------- launch --------
extern "C" void kernel_launch(void* const* d_in, const int* in_sizes, int n_in,
                              void* d_out, int out_size) {
    const float* x  = (const float*)d_in[0];
    const void*  ei = d_in[1];
    const float* W1 = (const float*)d_in[2];
    const float* b1 = (const float*)d_in[3];
    const float* W2 = (const float*)d_in[4];
    const float* b2 = (const float*)d_in[5];
    float* out = (float*)d_out;

    (void)in_sizes; (void)n_in; (void)out_size;

    k_gemm1_deg<<<GEMM1_BLOCKS + EDGE_BLOCKS, 256>>>(x, W1, ei);           // 0 (overlapped)
    k_scan<<<SCAN_NB, SCAN_BLK>>>();                                       // 1
    k_scatter<<<EDGE_BLOCKS, 256>>>(ei);                                   // 2
    k_agg1<<<(int)(((size_t)NN * 32 + 255) / 256), 256>>>(b1);             // 3  <- ncu capture slot
    k_gemm2<<<(NN + 127) / 128, 256>>>(W2);                                // 4
    k_agg2_logsm<<<(int)(((size_t)NN * 32 + 255) / 256), 256>>>(out, b2);  // 5
}

// round 13
// speedup vs baseline: 1.1390x; 1.1046x over previous
#include <cuda_runtime.h>
#include <cuda_fp16.h>
#include <cstdint>

#define NN 50000
#define NE 1600000
#define DIN 256
#define DH 128
#define DO 40

#define SCAN_BLK 512
#define SCAN_NB ((NN + SCAN_BLK - 1) / SCAN_BLK)   // 98

#define GEMM1_BLOCKS ((NN + 127) / 128)            // 391
#define EDGE_BLOCKS ((NE / 4 + 255) / 256)         // 1563

// -------- scratch (static device globals; no allocation allowed) --------
// g_deg is self-cleaning: k_scan zeroes it after reading (first run uses zero BSS).
static __device__ __align__(16) __half g_h1h[(size_t)NN * DH];   // x@W1 (fp16)
static __device__ __align__(16) __half g_a1h[(size_t)NN * DH];   // relu(agg1+b1) (fp16)
static __device__ __align__(16) __half g_h2h[(size_t)NN * DO];   // layer2 pre-agg (fp16)
static __device__ int      g_deg[NN];
static __device__ float    g_dinv[NN];
static __device__ int      g_off[NN];     // CSR row start
static __device__ int      g_pos[NN];     // CSR row end (off + deg), set by scan
static __device__ int      g_rank[NE];    // per-edge rank within its dst bucket
static __device__ unsigned g_edge[NE];    // packed: (src << 16) | fp16(coef)
static __device__ int      g_total;       // scan ticket (self-resetting)
static __device__ int      g_done;        // scan completion counter (self-resetting)

// -------- per-block edge dtype detection (odd 32-bit words all zero <=> int64) --------
__device__ __forceinline__ bool detect_is64(const int* __restrict__ ei32, int tid, int nthr) {
    __shared__ int s64;
    if (tid == 0) s64 = 1;
    __syncthreads();
    int any = 0;
    for (int i = tid; i < 2048; i += nthr) any |= ei32[2 * i + 1];
    if (any) s64 = 0;
    __syncthreads();
    return s64 != 0;
}

// -------- async copy / mma helpers --------
__device__ __forceinline__ void cp_async16(void* smem, const void* gmem, bool pred) {
    uint32_t sa = (uint32_t)__cvta_generic_to_shared(smem);
    int sz = pred ? 16 : 0;
    asm volatile("cp.async.cg.shared.global [%0], [%1], 16, %2;" :: "r"(sa), "l"(gmem), "r"(sz));
}
__device__ __forceinline__ void cp_commit() { asm volatile("cp.async.commit_group;"); }
template <int N>
__device__ __forceinline__ void cp_wait() { asm volatile("cp.async.wait_group %0;" :: "n"(N)); }

__device__ __forceinline__ void mma_tf32(float& d0, float& d1, float& d2, float& d3,
                                         uint32_t a0, uint32_t a1, uint32_t a2, uint32_t a3,
                                         uint32_t b0, uint32_t b1) {
    asm volatile(
        "mma.sync.aligned.m16n8k8.row.col.f32.tf32.tf32.f32 "
        "{%0,%1,%2,%3}, {%4,%5,%6,%7}, {%8,%9}, {%0,%1,%2,%3};"
        : "+f"(d0), "+f"(d1), "+f"(d2), "+f"(d3)
        : "r"(a0), "r"(a1), "r"(a2), "r"(a3), "r"(b0), "r"(b1));
}

__device__ __forceinline__ void mma_f16(float& d0, float& d1, float& d2, float& d3,
                                        uint32_t a0, uint32_t a1, uint32_t a2, uint32_t a3,
                                        uint32_t b0, uint32_t b1) {
    asm volatile(
        "mma.sync.aligned.m16n8k16.row.col.f32.f16.f16.f32 "
        "{%0,%1,%2,%3}, {%4,%5,%6,%7}, {%8,%9}, {%0,%1,%2,%3};"
        : "+f"(d0), "+f"(d1), "+f"(d2), "+f"(d3)
        : "r"(a0), "r"(a1), "r"(a2), "r"(a3), "r"(b0), "r"(b1));
}

__device__ __forceinline__ void ldmatrix_x4(uint32_t& r0, uint32_t& r1, uint32_t& r2, uint32_t& r3,
                                            uint32_t addr) {
    asm volatile("ldmatrix.sync.aligned.m8n8.x4.shared.b16 {%0,%1,%2,%3}, [%4];"
                 : "=r"(r0), "=r"(r1), "=r"(r2), "=r"(r3) : "r"(addr));
}
__device__ __forceinline__ void ldmatrix_x2(uint32_t& r0, uint32_t& r1, uint32_t addr) {
    asm volatile("ldmatrix.sync.aligned.m8n8.x2.shared.b16 {%0,%1}, [%2];"
                 : "=r"(r0), "=r"(r1) : "r"(addr));
}

// ======== COMBINED LAUNCH: blocks [0,391) = GEMM1, blocks [391,...) = degree+rank ========
#define LDA 20
#define LDB 136
#define NT (DIN / 16)   // 16 k-tiles

__device__ void gemm1_body(const float* __restrict__ X, const float* __restrict__ W,
                           int bid) {
    __shared__ __align__(16) uint32_t Ah[2][128 * LDA];
    __shared__ __align__(16) uint32_t Bh[2][16 * LDB];

    int tid = threadIdx.x;
    int lane = tid & 31;
    int wid = tid >> 5;
    int wm = wid & 3;
    int wn = wid >> 2;
    int g = lane >> 2;
    int t = lane & 3;
    int r0 = bid * 128;

    int arow = tid >> 2, ac4 = tid & 3;
    int brow = tid >> 5, bc4 = tid & 31;

    auto load_tile = [&](int it, int buf) {
#pragma unroll
        for (int q = 0; q < 2; q++) {
            int row = arow + q * 64;
            cp_async16(&Ah[buf][row * LDA + ac4 * 4],
                       X + (size_t)(r0 + row) * DIN + it * 16 + ac4 * 4,
                       r0 + row < NN);
        }
#pragma unroll
        for (int q = 0; q < 2; q++) {
            int kr = brow + q * 8;
            cp_async16(&Bh[buf][kr * LDB + bc4 * 4],
                       W + (size_t)(it * 16 + kr) * DH + bc4 * 4, true);
        }
    };

    float acc[2][8][4];
#pragma unroll
    for (int i = 0; i < 2; i++)
#pragma unroll
        for (int j = 0; j < 8; j++)
#pragma unroll
            for (int k = 0; k < 4; k++) acc[i][j][k] = 0.f;

    load_tile(0, 0);
    cp_commit();

    for (int it = 0; it < NT; it++) {
        int buf = it & 1;
        if (it + 1 < NT) {
            load_tile(it + 1, (it + 1) & 1);
            cp_commit();
            cp_wait<1>();
        } else {
            cp_wait<0>();
        }
        __syncthreads();

#pragma unroll
        for (int kk = 0; kk < 2; kk++) {
            int kb = kk * 8;
            uint32_t ah[2][4];
#pragma unroll
            for (int mt = 0; mt < 2; mt++) {
                int rbase = (wm * 32 + mt * 16) * LDA + kb + t;
                ah[mt][0] = Ah[buf][rbase + g * LDA];
                ah[mt][1] = Ah[buf][rbase + (g + 8) * LDA];
                ah[mt][2] = Ah[buf][rbase + g * LDA + 4];
                ah[mt][3] = Ah[buf][rbase + (g + 8) * LDA + 4];
            }
            uint32_t bh[8][2];
#pragma unroll
            for (int nt = 0; nt < 8; nt++) {
                int cbase = wn * 64 + nt * 8 + g;
                bh[nt][0] = Bh[buf][(kb + t) * LDB + cbase];
                bh[nt][1] = Bh[buf][(kb + t + 4) * LDB + cbase];
            }
#pragma unroll
            for (int mt = 0; mt < 2; mt++)
#pragma unroll
                for (int nt = 0; nt < 8; nt++) {
                    float* d = acc[mt][nt];
                    mma_tf32(d[0], d[1], d[2], d[3],
                             ah[mt][0], ah[mt][1], ah[mt][2], ah[mt][3],
                             bh[nt][0], bh[nt][1]);
                }
        }
        __syncthreads();
    }

#pragma unroll
    for (int mt = 0; mt < 2; mt++) {
#pragma unroll
        for (int nt = 0; nt < 8; nt++) {
            int col = wn * 64 + nt * 8 + 2 * t;
            int rowa = r0 + wm * 32 + mt * 16 + g;
            int rowb = rowa + 8;
            float* d = acc[mt][nt];
            if (rowa < NN)
                *(__half2*)(g_h1h + (size_t)rowa * DH + col) = __floats2half2_rn(d[0], d[1]);
            if (rowb < NN)
                *(__half2*)(g_h1h + (size_t)rowb * DH + col) = __floats2half2_rn(d[2], d[3]);
        }
    }
}

// degree + rank capture: the histogram atomic's return value IS the edge's rank
__device__ void deg_body(const void* __restrict__ ei, int bid, bool is64) {
    int t = bid * 256 + threadIdx.x;
    if (!is64) {
        if (t < NE / 4) {
            int4 d4 = ((const int4*)((const int*)ei + NE))[t];
            int dd[4] = {d4.x, d4.y, d4.z, d4.w};
            int rr[4] = {0, 0, 0, 0};
#pragma unroll
            for (int q = 0; q < 4; q++)
                if ((unsigned)dd[q] < NN) rr[q] = atomicAdd(&g_deg[dd[q]], 1);
            ((int4*)g_rank)[t] = make_int4(rr[0], rr[1], rr[2], rr[3]);
        }
    } else {
        for (int e = t * 4; e < t * 4 + 4 && e < NE; e++) {
            int d = (int)((const long long*)ei)[NE + e];
            int r = 0;
            if ((unsigned)d < NN) r = atomicAdd(&g_deg[d], 1);
            g_rank[e] = r;
        }
    }
}

__global__ void __launch_bounds__(256)
k_gemm1_deg(const float* __restrict__ X, const float* __restrict__ W,
            const void* __restrict__ ei) {
    if (blockIdx.x < GEMM1_BLOCKS) {
        gemm1_body(X, W, blockIdx.x);
    } else {
        bool is64 = detect_is64((const int*)ei, threadIdx.x, 256);
        deg_body(ei, blockIdx.x - GEMM1_BLOCKS, is64);
    }
}

// -------- ticket scan: g_off = row start, g_pos = row end, dinv; zero g_deg --------
__global__ void k_scan() {
    __shared__ int sh[SCAN_BLK];
    __shared__ int base;
    int t = threadIdx.x;
    int i = blockIdx.x * SCAN_BLK + t;
    int v = (i < NN) ? g_deg[i] : 0;
    if (i < NN) g_deg[i] = 0;        // self-clean (only this thread reads g_deg[i])
    sh[t] = v;
    __syncthreads();
#pragma unroll
    for (int o = 1; o < SCAN_BLK; o <<= 1) {
        int x = (t >= o) ? sh[t - o] : 0;
        __syncthreads();
        sh[t] += x;
        __syncthreads();
    }
    if (t == SCAN_BLK - 1) base = atomicAdd(&g_total, sh[t]);
    __syncthreads();
    if (i < NN) {
        int off = base + sh[t] - v;  // exclusive within arrival-ordered layout
        g_off[i] = off;
        g_pos[i] = off + v;          // row end
        g_dinv[i] = rsqrtf((float)(v + 1));
    }
    __threadfence();
    if (t == 0) {
        if (atomicAdd(&g_done, 1) == gridDim.x - 1) {
            g_total = 0;
            g_done = 0;
        }
    }
}

// -------- CSR fill, ATOMIC-FREE: slot = off[dst] + rank[e] --------
__global__ void __launch_bounds__(256) k_scatter(const void* __restrict__ ei) {
    bool is64 = detect_is64((const int*)ei, threadIdx.x, 256);
    int t = blockIdx.x * blockDim.x + threadIdx.x;
    if (!is64) {
        if (t < NE / 4) {
            int4 s4 = ((const int4*)ei)[t];
            int4 d4 = ((const int4*)((const int*)ei + NE))[t];
            int4 r4 = ((const int4*)g_rank)[t];
            int ss[4] = {s4.x, s4.y, s4.z, s4.w};
            int dd[4] = {d4.x, d4.y, d4.z, d4.w};
            int rr[4] = {r4.x, r4.y, r4.z, r4.w};
#pragma unroll
            for (int q = 0; q < 4; q++) {
                int s = ss[q], d = dd[q];
                if ((unsigned)s < NN && (unsigned)d < NN) {
                    int slot = g_off[d] + rr[q];
                    unsigned hb = __half_as_ushort(__float2half_rn(g_dinv[s] * g_dinv[d]));
                    g_edge[slot] = ((unsigned)s << 16) | hb;
                }
            }
        }
    } else {
        for (int e = t * 4; e < t * 4 + 4 && e < NE; e++) {
            int s = (int)((const long long*)ei)[e];
            int d = (int)((const long long*)ei)[NE + e];
            if ((unsigned)s < NN && (unsigned)d < NN) {
                int slot = g_off[d] + g_rank[e];
                unsigned hb = __half_as_ushort(__float2half_rn(g_dinv[s] * g_dinv[d]));
                g_edge[slot] = ((unsigned)s << 16) | hb;
            }
        }
    }
}

// -------- layer1 aggregation: warp per node, half-warp per edge, 8-edge unroll --------
__device__ __forceinline__ void acc_row(float* acc, uint4 u, float c) {
    float2 f0 = __half22float2(*(__half2*)&u.x);
    float2 f1 = __half22float2(*(__half2*)&u.y);
    float2 f2 = __half22float2(*(__half2*)&u.z);
    float2 f3 = __half22float2(*(__half2*)&u.w);
    acc[0] += c * f0.x; acc[1] += c * f0.y; acc[2] += c * f1.x; acc[3] += c * f1.y;
    acc[4] += c * f2.x; acc[5] += c * f2.y; acc[6] += c * f3.x; acc[7] += c * f3.y;
}

__global__ void k_agg1(const float* __restrict__ B1) {
    int t = blockIdx.x * blockDim.x + threadIdx.x;
    int w = t >> 5, lane = t & 31;
    if (w >= NN) return;
    int half = lane >> 4;
    int l = lane & 15;
    const uint4* __restrict__ H4 = (const uint4*)g_h1h;   // row = 16 uint4
    float acc[8];
#pragma unroll
    for (int i = 0; i < 8; i++) acc[i] = 0.f;

    float dv = g_dinv[w];
    if (half == 0) {
        float c0 = dv * dv;
        uint4 u = H4[(size_t)w * 16 + l];
        acc_row(acc, u, c0);
    }

    int j = g_off[w];
    int end = g_pos[w];
    for (; j + 8 <= end; j += 8) {
        unsigned e0 = g_edge[j + half];
        unsigned e1 = g_edge[j + 2 + half];
        unsigned e2 = g_edge[j + 4 + half];
        unsigned e3 = g_edge[j + 6 + half];
        uint4 u0 = H4[(size_t)(e0 >> 16) * 16 + l];
        uint4 u1 = H4[(size_t)(e1 >> 16) * 16 + l];
        uint4 u2 = H4[(size_t)(e2 >> 16) * 16 + l];
        uint4 u3 = H4[(size_t)(e3 >> 16) * 16 + l];
        acc_row(acc, u0, __half2float(__ushort_as_half((unsigned short)(e0 & 0xffffu))));
        acc_row(acc, u1, __half2float(__ushort_as_half((unsigned short)(e1 & 0xffffu))));
        acc_row(acc, u2, __half2float(__ushort_as_half((unsigned short)(e2 & 0xffffu))));
        acc_row(acc, u3, __half2float(__ushort_as_half((unsigned short)(e3 & 0xffffu))));
    }
    if (j + 4 <= end) {
        unsigned e0 = g_edge[j + half];
        unsigned e1 = g_edge[j + 2 + half];
        uint4 u0 = H4[(size_t)(e0 >> 16) * 16 + l];
        uint4 u1 = H4[(size_t)(e1 >> 16) * 16 + l];
        acc_row(acc, u0, __half2float(__ushort_as_half((unsigned short)(e0 & 0xffffu))));
        acc_row(acc, u1, __half2float(__ushort_as_half((unsigned short)(e1 & 0xffffu))));
        j += 4;
    }
    if (j + 2 <= end) {
        unsigned e0 = g_edge[j + half];
        uint4 u0 = H4[(size_t)(e0 >> 16) * 16 + l];
        acc_row(acc, u0, __half2float(__ushort_as_half((unsigned short)(e0 & 0xffffu))));
        j += 2;
    }
    if (j < end && half == 0) {
        unsigned e0 = g_edge[j];
        uint4 u0 = H4[(size_t)(e0 >> 16) * 16 + l];
        acc_row(acc, u0, __half2float(__ushort_as_half((unsigned short)(e0 & 0xffffu))));
    }

#pragma unroll
    for (int i = 0; i < 8; i++) acc[i] += __shfl_xor_sync(0xffffffffu, acc[i], 16);

    if (half == 0) {
        float4 b0 = ((const float4*)B1)[2 * l];
        float4 b1v = ((const float4*)B1)[2 * l + 1];
        acc[0] = fmaxf(acc[0] + b0.x, 0.f); acc[1] = fmaxf(acc[1] + b0.y, 0.f);
        acc[2] = fmaxf(acc[2] + b0.z, 0.f); acc[3] = fmaxf(acc[3] + b0.w, 0.f);
        acc[4] = fmaxf(acc[4] + b1v.x, 0.f); acc[5] = fmaxf(acc[5] + b1v.y, 0.f);
        acc[6] = fmaxf(acc[6] + b1v.z, 0.f); acc[7] = fmaxf(acc[7] + b1v.w, 0.f);
        __half2 h0 = __floats2half2_rn(acc[0], acc[1]);
        __half2 h1 = __floats2half2_rn(acc[2], acc[3]);
        __half2 h2 = __floats2half2_rn(acc[4], acc[5]);
        __half2 h3 = __floats2half2_rn(acc[6], acc[7]);
        uint4 st;
        st.x = *(unsigned*)&h0; st.y = *(unsigned*)&h1;
        st.z = *(unsigned*)&h2; st.w = *(unsigned*)&h3;
        ((uint4*)g_a1h)[(size_t)w * 16 + l] = st;
    }
}

// -------- GEMM2 (fp16 tensor cores): h2h[NN,40] = a1h[NN,128] @ fp16(W2)[128,40] --------
// BM=128, full K=128 staged once; 8 warps x (m16 tile each) x 5 n8-tiles x 8 k16-steps.
#define LD2 136
__global__ void __launch_bounds__(256) k_gemm2(const float* __restrict__ W2) {
    __shared__ __align__(16) __half As[128 * LD2];
    __shared__ __align__(16) __half Bs[40 * LD2];
    int tid = threadIdx.x;
    int r0 = blockIdx.x * 128;

    // stage A (fp16) via cp.async: 128 rows x 16 chunks of 16B
#pragma unroll
    for (int q = 0; q < 8; q++) {
        int id = tid + q * 256;
        int row = id >> 4, ch = id & 15;
        cp_async16(&As[row * LD2 + ch * 8],
                   g_a1h + (size_t)(r0 + row) * DH + ch * 8,
                   r0 + row < NN);
    }
    cp_commit();
    // stage B transposed: Bs[n][k] = fp16(W2[k][n])
#pragma unroll
    for (int q = 0; q < 20; q++) {
        int id = tid + q * 256;
        int k = id / 40, n = id % 40;
        Bs[n * LD2 + k] = __float2half_rn(W2[id]);
    }
    cp_wait<0>();
    __syncthreads();

    int lane = tid & 31, wid = tid >> 5;
    int g = lane >> 2, t = lane & 3;

    float acc[5][4];
#pragma unroll
    for (int nt = 0; nt < 5; nt++)
#pragma unroll
        for (int i = 0; i < 4; i++) acc[nt][i] = 0.f;

    // A ldmatrix address: lanes 0-7 rows 0-7 (k+0), 8-15 rows 8-15 (k+0),
    // 16-23 rows 0-7 (k+8), 24-31 rows 8-15 (k+8)
    int arow = wid * 16 + (lane & 7) + ((lane & 8) ? 8 : 0);
    int acol = (lane & 16) ? 8 : 0;
    uint32_t abase = (uint32_t)__cvta_generic_to_shared(&As[arow * LD2]);
    // B ldmatrix (x2, lanes 0-15): lanes 0-7 rows n+0..7 (k+0), 8-15 same rows (k+8)
    int bl = lane & 15;
    int brow = bl & 7;
    int bcol = (bl & 8) ? 8 : 0;

#pragma unroll
    for (int ks = 0; ks < 8; ks++) {
        uint32_t a0, a1, a2, a3;
        ldmatrix_x4(a0, a1, a2, a3, abase + (uint32_t)(16 * ks + acol) * 2);
#pragma unroll
        for (int nt = 0; nt < 5; nt++) {
            uint32_t b0, b1;
            uint32_t baddr = (uint32_t)__cvta_generic_to_shared(
                &Bs[(8 * nt + brow) * LD2 + 16 * ks + bcol]);
            ldmatrix_x2(b0, b1, baddr);
            mma_f16(acc[nt][0], acc[nt][1], acc[nt][2], acc[nt][3],
                    a0, a1, a2, a3, b0, b1);
        }
    }

#pragma unroll
    for (int nt = 0; nt < 5; nt++) {
        int col = nt * 8 + 2 * t;
        int ra = r0 + wid * 16 + g;
        int rb = ra + 8;
        if (ra < NN)
            *(__half2*)(g_h2h + (size_t)ra * DO + col) = __floats2half2_rn(acc[nt][0], acc[nt][1]);
        if (rb < NN)
            *(__half2*)(g_h2h + (size_t)rb * DO + col) = __floats2half2_rn(acc[nt][2], acc[nt][3]);
    }
}

// -------- layer2 aggregation + bias + log_softmax fused, 4x unroll --------
__global__ void k_agg2_logsm(float* __restrict__ out, const float* __restrict__ B2) {
    int t = blockIdx.x * blockDim.x + threadIdx.x;
    int w = t >> 5, lane = t & 31;
    if (w >= NN) return;
    bool act = lane < 20;
    float dv = g_dinv[w];
    float c0 = dv * dv;
    const __half2* __restrict__ Hh = (const __half2*)g_h2h;
    float acc0 = 0.f, acc1 = 0.f;
    if (act) {
        float2 f = __half22float2(Hh[(size_t)w * 20 + lane]);
        acc0 = c0 * f.x;
        acc1 = c0 * f.y;
    }
    int j = g_off[w];
    int end = g_pos[w];
    int lidx = act ? lane : 0;
    for (; j + 4 <= end; j += 4) {
        unsigned ew[4];
#pragma unroll
        for (int q = 0; q < 4; q++) ew[q] = g_edge[j + q];
        __half2 u[4];
#pragma unroll
        for (int q = 0; q < 4; q++) u[q] = Hh[(size_t)(ew[q] >> 16) * 20 + lidx];
        if (act) {
#pragma unroll
            for (int q = 0; q < 4; q++) {
                float c = __half2float(__ushort_as_half((unsigned short)(ew[q] & 0xffffu)));
                float2 f = __half22float2(u[q]);
                acc0 += c * f.x;
                acc1 += c * f.y;
            }
        }
    }
    for (; j < end; j++) {
        unsigned e0 = g_edge[j];
        float2 f = __half22float2(Hh[(size_t)(e0 >> 16) * 20 + lidx]);
        if (act) {
            float c = __half2float(__ushort_as_half((unsigned short)(e0 & 0xffffu)));
            acc0 += c * f.x;
            acc1 += c * f.y;
        }
    }
    if (act) {
        acc0 += B2[2 * lane];
        acc1 += B2[2 * lane + 1];
    }
    float m = act ? fmaxf(acc0, acc1) : __int_as_float(0xff800000);
#pragma unroll
    for (int o = 16; o > 0; o >>= 1) m = fmaxf(m, __shfl_xor_sync(0xffffffffu, m, o));
    float s = act ? (expf(acc0 - m) + expf(acc1 - m)) : 0.f;
#pragma unroll
    for (int o = 16; o > 0; o >>= 1) s += __shfl_xor_sync(0xffffffffu, s, o);
    float lse = m + logf(s);
    if (act)
        *(float2*)(out + (size_t)w * DO + 2 * lane) = make_float2(acc0 - lse, acc1 - lse);
}

// -------- launch --------
extern "C" void kernel_launch(void* const* d_in, const int* in_sizes, int n_in,
                              void* d_out, int out_size) {
    const float* x  = (const float*)d_in[0];
    const void*  ei = d_in[1];
    const float* W1 = (const float*)d_in[2];
    const float* b1 = (const float*)d_in[3];
    const float* W2 = (const float*)d_in[4];
    const float* b2 = (const float*)d_in[5];
    float* out = (float*)d_out;

    (void)in_sizes; (void)n_in; (void)out_size;

    k_gemm1_deg<<<GEMM1_BLOCKS + EDGE_BLOCKS, 256>>>(x, W1, ei);           // 0 (overlapped)
    k_scan<<<SCAN_NB, SCAN_BLK>>>();                                       // 1
    k_scatter<<<EDGE_BLOCKS, 256>>>(ei);                                   // 2
    k_agg1<<<(int)(((size_t)NN * 32 + 255) / 256), 256>>>(b1);             // 3  <- ncu capture slot
    k_gemm2<<<(NN + 127) / 128, 256>>>(W2);                                // 4
    k_agg2_logsm<<<(int)(((size_t)NN * 32 + 255) / 256), 256>>>(out, b2);  // 5
}

// round 14
// speedup vs baseline: 1.1842x; 1.0397x over previous
#include <cuda_runtime.h>
#include <cuda_fp16.h>
#include <cstdint>

#define NN 50000
#define NE 1600000
#define DIN 256
#define DH 128
#define DO 40

#define SCAN_BLK 512
#define SCAN_NB ((NN + SCAN_BLK - 1) / SCAN_BLK)   // 98

#define GEMM1_BLOCKS ((NN + 127) / 128)            // 391
#define EDGE_BLOCKS ((NE / 4 + 255) / 256)         // 1563

// -------- scratch (static device globals; no allocation allowed) --------
// g_deg is self-cleaning: k_scan zeroes it after reading (first run uses zero BSS).
static __device__ __align__(16) __half g_h1h[(size_t)NN * DH];   // x@W1 (fp16)
static __device__ __align__(16) __half g_a1h[(size_t)NN * DH];   // relu(agg1+b1) (fp16)
static __device__ __align__(16) __half g_h2h[(size_t)NN * DO];   // layer2 pre-agg (fp16)
static __device__ int      g_deg[NN];
static __device__ float    g_dinv[NN];
static __device__ int      g_off[NN];     // CSR row start
static __device__ int      g_pos[NN];     // CSR row end (off + deg), set by scan
static __device__ int      g_rank[NE];    // per-edge rank within its dst bucket
static __device__ unsigned g_edge[NE];    // packed: (src << 16) | fp16(coef)
static __device__ int      g_total;       // scan ticket (self-resetting)
static __device__ int      g_done;        // scan completion counter (self-resetting)

// -------- per-block edge dtype detection (odd 32-bit words all zero <=> int64) --------
__device__ __forceinline__ bool detect_is64(const int* __restrict__ ei32, int tid, int nthr) {
    __shared__ int s64;
    if (tid == 0) s64 = 1;
    __syncthreads();
    int any = 0;
    for (int i = tid; i < 2048; i += nthr) any |= ei32[2 * i + 1];
    if (any) s64 = 0;
    __syncthreads();
    return s64 != 0;
}

// -------- async copy / mma helpers --------
__device__ __forceinline__ void cp_async16(void* smem, const void* gmem, bool pred) {
    uint32_t sa = (uint32_t)__cvta_generic_to_shared(smem);
    int sz = pred ? 16 : 0;
    asm volatile("cp.async.cg.shared.global [%0], [%1], 16, %2;" :: "r"(sa), "l"(gmem), "r"(sz));
}
__device__ __forceinline__ void cp_commit() { asm volatile("cp.async.commit_group;"); }
template <int N>
__device__ __forceinline__ void cp_wait() { asm volatile("cp.async.wait_group %0;" :: "n"(N)); }

__device__ __forceinline__ void mma_tf32(float& d0, float& d1, float& d2, float& d3,
                                         uint32_t a0, uint32_t a1, uint32_t a2, uint32_t a3,
                                         uint32_t b0, uint32_t b1) {
    asm volatile(
        "mma.sync.aligned.m16n8k8.row.col.f32.tf32.tf32.f32 "
        "{%0,%1,%2,%3}, {%4,%5,%6,%7}, {%8,%9}, {%0,%1,%2,%3};"
        : "+f"(d0), "+f"(d1), "+f"(d2), "+f"(d3)
        : "r"(a0), "r"(a1), "r"(a2), "r"(a3), "r"(b0), "r"(b1));
}

__device__ __forceinline__ void mma_f16(float& d0, float& d1, float& d2, float& d3,
                                        uint32_t a0, uint32_t a1, uint32_t a2, uint32_t a3,
                                        uint32_t b0, uint32_t b1) {
    asm volatile(
        "mma.sync.aligned.m16n8k16.row.col.f32.f16.f16.f32 "
        "{%0,%1,%2,%3}, {%4,%5,%6,%7}, {%8,%9}, {%0,%1,%2,%3};"
        : "+f"(d0), "+f"(d1), "+f"(d2), "+f"(d3)
        : "r"(a0), "r"(a1), "r"(a2), "r"(a3), "r"(b0), "r"(b1));
}

__device__ __forceinline__ void ldmatrix_x4(uint32_t& r0, uint32_t& r1, uint32_t& r2, uint32_t& r3,
                                            uint32_t addr) {
    asm volatile("ldmatrix.sync.aligned.m8n8.x4.shared.b16 {%0,%1,%2,%3}, [%4];"
                 : "=r"(r0), "=r"(r1), "=r"(r2), "=r"(r3) : "r"(addr));
}
__device__ __forceinline__ void ldmatrix_x2(uint32_t& r0, uint32_t& r1, uint32_t addr) {
    asm volatile("ldmatrix.sync.aligned.m8n8.x2.shared.b16 {%0,%1}, [%2];"
                 : "=r"(r0), "=r"(r1) : "r"(addr));
}

// ======== COMBINED LAUNCH: blocks [0,391) = GEMM1, blocks [391,...) = degree+rank ========
#define LDA 20
#define LDB 136
#define NT (DIN / 16)   // 16 k-tiles

__device__ void gemm1_body(const float* __restrict__ X, const float* __restrict__ W,
                           int bid) {
    __shared__ __align__(16) uint32_t Ah[2][128 * LDA];
    __shared__ __align__(16) uint32_t Bh[2][16 * LDB];

    int tid = threadIdx.x;
    int lane = tid & 31;
    int wid = tid >> 5;
    int wm = wid & 3;
    int wn = wid >> 2;
    int g = lane >> 2;
    int t = lane & 3;
    int r0 = bid * 128;

    int arow = tid >> 2, ac4 = tid & 3;
    int brow = tid >> 5, bc4 = tid & 31;

    auto load_tile = [&](int it, int buf) {
#pragma unroll
        for (int q = 0; q < 2; q++) {
            int row = arow + q * 64;
            cp_async16(&Ah[buf][row * LDA + ac4 * 4],
                       X + (size_t)(r0 + row) * DIN + it * 16 + ac4 * 4,
                       r0 + row < NN);
        }
#pragma unroll
        for (int q = 0; q < 2; q++) {
            int kr = brow + q * 8;
            cp_async16(&Bh[buf][kr * LDB + bc4 * 4],
                       W + (size_t)(it * 16 + kr) * DH + bc4 * 4, true);
        }
    };

    float acc[2][8][4];
#pragma unroll
    for (int i = 0; i < 2; i++)
#pragma unroll
        for (int j = 0; j < 8; j++)
#pragma unroll
            for (int k = 0; k < 4; k++) acc[i][j][k] = 0.f;

    load_tile(0, 0);
    cp_commit();

    for (int it = 0; it < NT; it++) {
        int buf = it & 1;
        if (it + 1 < NT) {
            load_tile(it + 1, (it + 1) & 1);
            cp_commit();
            cp_wait<1>();
        } else {
            cp_wait<0>();
        }
        __syncthreads();

#pragma unroll
        for (int kk = 0; kk < 2; kk++) {
            int kb = kk * 8;
            uint32_t ah[2][4];
#pragma unroll
            for (int mt = 0; mt < 2; mt++) {
                int rbase = (wm * 32 + mt * 16) * LDA + kb + t;
                ah[mt][0] = Ah[buf][rbase + g * LDA];
                ah[mt][1] = Ah[buf][rbase + (g + 8) * LDA];
                ah[mt][2] = Ah[buf][rbase + g * LDA + 4];
                ah[mt][3] = Ah[buf][rbase + (g + 8) * LDA + 4];
            }
            uint32_t bh[8][2];
#pragma unroll
            for (int nt = 0; nt < 8; nt++) {
                int cbase = wn * 64 + nt * 8 + g;
                bh[nt][0] = Bh[buf][(kb + t) * LDB + cbase];
                bh[nt][1] = Bh[buf][(kb + t + 4) * LDB + cbase];
            }
#pragma unroll
            for (int mt = 0; mt < 2; mt++)
#pragma unroll
                for (int nt = 0; nt < 8; nt++) {
                    float* d = acc[mt][nt];
                    mma_tf32(d[0], d[1], d[2], d[3],
                             ah[mt][0], ah[mt][1], ah[mt][2], ah[mt][3],
                             bh[nt][0], bh[nt][1]);
                }
        }
        __syncthreads();
    }

#pragma unroll
    for (int mt = 0; mt < 2; mt++) {
#pragma unroll
        for (int nt = 0; nt < 8; nt++) {
            int col = wn * 64 + nt * 8 + 2 * t;
            int rowa = r0 + wm * 32 + mt * 16 + g;
            int rowb = rowa + 8;
            float* d = acc[mt][nt];
            if (rowa < NN)
                *(__half2*)(g_h1h + (size_t)rowa * DH + col) = __floats2half2_rn(d[0], d[1]);
            if (rowb < NN)
                *(__half2*)(g_h1h + (size_t)rowb * DH + col) = __floats2half2_rn(d[2], d[3]);
        }
    }
}

// degree + rank capture: the histogram atomic's return value IS the edge's rank
__device__ void deg_body(const void* __restrict__ ei, int bid, bool is64) {
    int t = bid * 256 + threadIdx.x;
    if (!is64) {
        if (t < NE / 4) {
            int4 d4 = ((const int4*)((const int*)ei + NE))[t];
            int dd[4] = {d4.x, d4.y, d4.z, d4.w};
            int rr[4] = {0, 0, 0, 0};
#pragma unroll
            for (int q = 0; q < 4; q++)
                if ((unsigned)dd[q] < NN) rr[q] = atomicAdd(&g_deg[dd[q]], 1);
            ((int4*)g_rank)[t] = make_int4(rr[0], rr[1], rr[2], rr[3]);
        }
    } else {
        for (int e = t * 4; e < t * 4 + 4 && e < NE; e++) {
            int d = (int)((const long long*)ei)[NE + e];
            int r = 0;
            if ((unsigned)d < NN) r = atomicAdd(&g_deg[d], 1);
            g_rank[e] = r;
        }
    }
}

__global__ void __launch_bounds__(256)
k_gemm1_deg(const float* __restrict__ X, const float* __restrict__ W,
            const void* __restrict__ ei) {
    if (blockIdx.x < GEMM1_BLOCKS) {
        gemm1_body(X, W, blockIdx.x);
    } else {
        bool is64 = detect_is64((const int*)ei, threadIdx.x, 256);
        deg_body(ei, blockIdx.x - GEMM1_BLOCKS, is64);
    }
}

// -------- ticket scan: g_off = row start, g_pos = row end, dinv; zero g_deg --------
__global__ void k_scan() {
    __shared__ int sh[SCAN_BLK];
    __shared__ int base;
    int t = threadIdx.x;
    int i = blockIdx.x * SCAN_BLK + t;
    int v = (i < NN) ? g_deg[i] : 0;
    if (i < NN) g_deg[i] = 0;        // self-clean (only this thread reads g_deg[i])
    sh[t] = v;
    __syncthreads();
#pragma unroll
    for (int o = 1; o < SCAN_BLK; o <<= 1) {
        int x = (t >= o) ? sh[t - o] : 0;
        __syncthreads();
        sh[t] += x;
        __syncthreads();
    }
    if (t == SCAN_BLK - 1) base = atomicAdd(&g_total, sh[t]);
    __syncthreads();
    if (i < NN) {
        int off = base + sh[t] - v;  // exclusive within arrival-ordered layout
        g_off[i] = off;
        g_pos[i] = off + v;          // row end
        g_dinv[i] = rsqrtf((float)(v + 1));
    }
    __threadfence();
    if (t == 0) {
        if (atomicAdd(&g_done, 1) == gridDim.x - 1) {
            g_total = 0;
            g_done = 0;
        }
    }
}

// -------- CSR fill, ATOMIC-FREE: slot = off[dst] + rank[e] --------
__global__ void __launch_bounds__(256) k_scatter(const void* __restrict__ ei) {
    bool is64 = detect_is64((const int*)ei, threadIdx.x, 256);
    int t = blockIdx.x * blockDim.x + threadIdx.x;
    if (!is64) {
        if (t < NE / 4) {
            int4 s4 = ((const int4*)ei)[t];
            int4 d4 = ((const int4*)((const int*)ei + NE))[t];
            int4 r4 = ((const int4*)g_rank)[t];
            int ss[4] = {s4.x, s4.y, s4.z, s4.w};
            int dd[4] = {d4.x, d4.y, d4.z, d4.w};
            int rr[4] = {r4.x, r4.y, r4.z, r4.w};
#pragma unroll
            for (int q = 0; q < 4; q++) {
                int s = ss[q], d = dd[q];
                if ((unsigned)s < NN && (unsigned)d < NN) {
                    int slot = g_off[d] + rr[q];
                    unsigned hb = __half_as_ushort(__float2half_rn(g_dinv[s] * g_dinv[d]));
                    g_edge[slot] = ((unsigned)s << 16) | hb;
                }
            }
        }
    } else {
        for (int e = t * 4; e < t * 4 + 4 && e < NE; e++) {
            int s = (int)((const long long*)ei)[e];
            int d = (int)((const long long*)ei)[NE + e];
            if ((unsigned)s < NN && (unsigned)d < NN) {
                int slot = g_off[d] + g_rank[e];
                unsigned hb = __half_as_ushort(__float2half_rn(g_dinv[s] * g_dinv[d]));
                g_edge[slot] = ((unsigned)s << 16) | hb;
            }
        }
    }
}

// -------- layer1 aggregation: warp per node, half-warp per edge --------
// fp16 HFMA2 accumulation in groups of 4 edges per half, flushed to fp32.
__device__ __forceinline__ void acc_row(float* acc, uint4 u, float c) {
    float2 f0 = __half22float2(*(__half2*)&u.x);
    float2 f1 = __half22float2(*(__half2*)&u.y);
    float2 f2 = __half22float2(*(__half2*)&u.z);
    float2 f3 = __half22float2(*(__half2*)&u.w);
    acc[0] += c * f0.x; acc[1] += c * f0.y; acc[2] += c * f1.x; acc[3] += c * f1.y;
    acc[4] += c * f2.x; acc[5] += c * f2.y; acc[6] += c * f3.x; acc[7] += c * f3.y;
}

__global__ void k_agg1(const float* __restrict__ B1) {
    int t = blockIdx.x * blockDim.x + threadIdx.x;
    int w = t >> 5, lane = t & 31;
    if (w >= NN) return;
    int half = lane >> 4;
    int l = lane & 15;
    const uint4* __restrict__ H4 = (const uint4*)g_h1h;   // row = 16 uint4
    float acc[8];
#pragma unroll
    for (int i = 0; i < 8; i++) acc[i] = 0.f;

    float dv = g_dinv[w];
    if (half == 0) {
        float c0 = dv * dv;
        uint4 u = H4[(size_t)w * 16 + l];
        acc_row(acc, u, c0);
    }

    int j = g_off[w];
    int end = g_pos[w];
    // group of 8 edges (4 per half), fp16 accumulation then fp32 flush
    for (; j + 8 <= end; j += 8) {
        unsigned e0 = g_edge[j + half];
        unsigned e1 = g_edge[j + 2 + half];
        unsigned e2 = g_edge[j + 4 + half];
        unsigned e3 = g_edge[j + 6 + half];
        uint4 u0 = H4[(size_t)(e0 >> 16) * 16 + l];
        uint4 u1 = H4[(size_t)(e1 >> 16) * 16 + l];
        uint4 u2 = H4[(size_t)(e2 >> 16) * 16 + l];
        uint4 u3 = H4[(size_t)(e3 >> 16) * 16 + l];
        __half2 c0 = __half2half2(__ushort_as_half((unsigned short)(e0 & 0xffffu)));
        __half2 c1 = __half2half2(__ushort_as_half((unsigned short)(e1 & 0xffffu)));
        __half2 c2 = __half2half2(__ushort_as_half((unsigned short)(e2 & 0xffffu)));
        __half2 c3 = __half2half2(__ushort_as_half((unsigned short)(e3 & 0xffffu)));
        __half2 ha = __hmul2(*(__half2*)&u0.x, c0);
        __half2 hb = __hmul2(*(__half2*)&u0.y, c0);
        __half2 hc = __hmul2(*(__half2*)&u0.z, c0);
        __half2 hd = __hmul2(*(__half2*)&u0.w, c0);
        ha = __hfma2(*(__half2*)&u1.x, c1, ha);
        hb = __hfma2(*(__half2*)&u1.y, c1, hb);
        hc = __hfma2(*(__half2*)&u1.z, c1, hc);
        hd = __hfma2(*(__half2*)&u1.w, c1, hd);
        ha = __hfma2(*(__half2*)&u2.x, c2, ha);
        hb = __hfma2(*(__half2*)&u2.y, c2, hb);
        hc = __hfma2(*(__half2*)&u2.z, c2, hc);
        hd = __hfma2(*(__half2*)&u2.w, c2, hd);
        ha = __hfma2(*(__half2*)&u3.x, c3, ha);
        hb = __hfma2(*(__half2*)&u3.y, c3, hb);
        hc = __hfma2(*(__half2*)&u3.z, c3, hc);
        hd = __hfma2(*(__half2*)&u3.w, c3, hd);
        float2 fa = __half22float2(ha);
        float2 fb = __half22float2(hb);
        float2 fc = __half22float2(hc);
        float2 fd = __half22float2(hd);
        acc[0] += fa.x; acc[1] += fa.y; acc[2] += fb.x; acc[3] += fb.y;
        acc[4] += fc.x; acc[5] += fc.y; acc[6] += fd.x; acc[7] += fd.y;
    }
    // tail (<8 edges) in exact fp32 path
    if (j + 4 <= end) {
        unsigned e0 = g_edge[j + half];
        unsigned e1 = g_edge[j + 2 + half];
        uint4 u0 = H4[(size_t)(e0 >> 16) * 16 + l];
        uint4 u1 = H4[(size_t)(e1 >> 16) * 16 + l];
        acc_row(acc, u0, __half2float(__ushort_as_half((unsigned short)(e0 & 0xffffu))));
        acc_row(acc, u1, __half2float(__ushort_as_half((unsigned short)(e1 & 0xffffu))));
        j += 4;
    }
    if (j + 2 <= end) {
        unsigned e0 = g_edge[j + half];
        uint4 u0 = H4[(size_t)(e0 >> 16) * 16 + l];
        acc_row(acc, u0, __half2float(__ushort_as_half((unsigned short)(e0 & 0xffffu))));
        j += 2;
    }
    if (j < end && half == 0) {
        unsigned e0 = g_edge[j];
        uint4 u0 = H4[(size_t)(e0 >> 16) * 16 + l];
        acc_row(acc, u0, __half2float(__ushort_as_half((unsigned short)(e0 & 0xffffu))));
    }

#pragma unroll
    for (int i = 0; i < 8; i++) acc[i] += __shfl_xor_sync(0xffffffffu, acc[i], 16);

    if (half == 0) {
        float4 b0 = ((const float4*)B1)[2 * l];
        float4 b1v = ((const float4*)B1)[2 * l + 1];
        acc[0] = fmaxf(acc[0] + b0.x, 0.f); acc[1] = fmaxf(acc[1] + b0.y, 0.f);
        acc[2] = fmaxf(acc[2] + b0.z, 0.f); acc[3] = fmaxf(acc[3] + b0.w, 0.f);
        acc[4] = fmaxf(acc[4] + b1v.x, 0.f); acc[5] = fmaxf(acc[5] + b1v.y, 0.f);
        acc[6] = fmaxf(acc[6] + b1v.z, 0.f); acc[7] = fmaxf(acc[7] + b1v.w, 0.f);
        __half2 h0 = __floats2half2_rn(acc[0], acc[1]);
        __half2 h1 = __floats2half2_rn(acc[2], acc[3]);
        __half2 h2 = __floats2half2_rn(acc[4], acc[5]);
        __half2 h3 = __floats2half2_rn(acc[6], acc[7]);
        uint4 st;
        st.x = *(unsigned*)&h0; st.y = *(unsigned*)&h1;
        st.z = *(unsigned*)&h2; st.w = *(unsigned*)&h3;
        ((uint4*)g_a1h)[(size_t)w * 16 + l] = st;
    }
}

// -------- GEMM2 (fp16 tensor cores): h2h[NN,40] = a1h[NN,128] @ fp16(W2)[128,40] --------
#define LD2 136
__global__ void __launch_bounds__(256) k_gemm2(const float* __restrict__ W2) {
    __shared__ __align__(16) __half As[128 * LD2];
    __shared__ __align__(16) __half Bs[40 * LD2];
    int tid = threadIdx.x;
    int r0 = blockIdx.x * 128;

#pragma unroll
    for (int q = 0; q < 8; q++) {
        int id = tid + q * 256;
        int row = id >> 4, ch = id & 15;
        cp_async16(&As[row * LD2 + ch * 8],
                   g_a1h + (size_t)(r0 + row) * DH + ch * 8,
                   r0 + row < NN);
    }
    cp_commit();
#pragma unroll
    for (int q = 0; q < 20; q++) {
        int id = tid + q * 256;
        int k = id / 40, n = id % 40;
        Bs[n * LD2 + k] = __float2half_rn(W2[id]);
    }
    cp_wait<0>();
    __syncthreads();

    int lane = tid & 31, wid = tid >> 5;
    int g = lane >> 2, t = lane & 3;

    float acc[5][4];
#pragma unroll
    for (int nt = 0; nt < 5; nt++)
#pragma unroll
        for (int i = 0; i < 4; i++) acc[nt][i] = 0.f;

    int arow = wid * 16 + (lane & 7) + ((lane & 8) ? 8 : 0);
    int acol = (lane & 16) ? 8 : 0;
    uint32_t abase = (uint32_t)__cvta_generic_to_shared(&As[arow * LD2]);
    int bl = lane & 15;
    int brow = bl & 7;
    int bcol = (bl & 8) ? 8 : 0;

#pragma unroll
    for (int ks = 0; ks < 8; ks++) {
        uint32_t a0, a1, a2, a3;
        ldmatrix_x4(a0, a1, a2, a3, abase + (uint32_t)(16 * ks + acol) * 2);
#pragma unroll
        for (int nt = 0; nt < 5; nt++) {
            uint32_t b0, b1;
            uint32_t baddr = (uint32_t)__cvta_generic_to_shared(
                &Bs[(8 * nt + brow) * LD2 + 16 * ks + bcol]);
            ldmatrix_x2(b0, b1, baddr);
            mma_f16(acc[nt][0], acc[nt][1], acc[nt][2], acc[nt][3],
                    a0, a1, a2, a3, b0, b1);
        }
    }

#pragma unroll
    for (int nt = 0; nt < 5; nt++) {
        int col = nt * 8 + 2 * t;
        int ra = r0 + wid * 16 + g;
        int rb = ra + 8;
        if (ra < NN)
            *(__half2*)(g_h2h + (size_t)ra * DO + col) = __floats2half2_rn(acc[nt][0], acc[nt][1]);
        if (rb < NN)
            *(__half2*)(g_h2h + (size_t)rb * DO + col) = __floats2half2_rn(acc[nt][2], acc[nt][3]);
    }
}

// -------- layer2 aggregation + bias + log_softmax fused --------
// fp16 HFMA2 accumulation in groups of 4 edges, flushed to fp32.
__global__ void k_agg2_logsm(float* __restrict__ out, const float* __restrict__ B2) {
    int t = blockIdx.x * blockDim.x + threadIdx.x;
    int w = t >> 5, lane = t & 31;
    if (w >= NN) return;
    bool act = lane < 20;
    float dv = g_dinv[w];
    float c0s = dv * dv;
    const __half2* __restrict__ Hh = (const __half2*)g_h2h;
    float acc0 = 0.f, acc1 = 0.f;
    if (act) {
        float2 f = __half22float2(Hh[(size_t)w * 20 + lane]);
        acc0 = c0s * f.x;
        acc1 = c0s * f.y;
    }
    int j = g_off[w];
    int end = g_pos[w];
    int lidx = act ? lane : 0;
    for (; j + 4 <= end; j += 4) {
        unsigned e0 = g_edge[j];
        unsigned e1 = g_edge[j + 1];
        unsigned e2 = g_edge[j + 2];
        unsigned e3 = g_edge[j + 3];
        __half2 u0 = Hh[(size_t)(e0 >> 16) * 20 + lidx];
        __half2 u1 = Hh[(size_t)(e1 >> 16) * 20 + lidx];
        __half2 u2 = Hh[(size_t)(e2 >> 16) * 20 + lidx];
        __half2 u3 = Hh[(size_t)(e3 >> 16) * 20 + lidx];
        __half2 c0 = __half2half2(__ushort_as_half((unsigned short)(e0 & 0xffffu)));
        __half2 c1 = __half2half2(__ushort_as_half((unsigned short)(e1 & 0xffffu)));
        __half2 c2 = __half2half2(__ushort_as_half((unsigned short)(e2 & 0xffffu)));
        __half2 c3 = __half2half2(__ushort_as_half((unsigned short)(e3 & 0xffffu)));
        __half2 h = __hmul2(u0, c0);
        h = __hfma2(u1, c1, h);
        h = __hfma2(u2, c2, h);
        h = __hfma2(u3, c3, h);
        if (act) {
            float2 f = __half22float2(h);
            acc0 += f.x;
            acc1 += f.y;
        }
    }
    for (; j < end; j++) {
        unsigned e0 = g_edge[j];
        float2 f = __half22float2(Hh[(size_t)(e0 >> 16) * 20 + lidx]);
        if (act) {
            float c = __half2float(__ushort_as_half((unsigned short)(e0 & 0xffffu)));
            acc0 += c * f.x;
            acc1 += c * f.y;
        }
    }
    if (act) {
        acc0 += B2[2 * lane];
        acc1 += B2[2 * lane + 1];
    }
    float m = act ? fmaxf(acc0, acc1) : __int_as_float(0xff800000);
#pragma unroll
    for (int o = 16; o > 0; o >>= 1) m = fmaxf(m, __shfl_xor_sync(0xffffffffu, m, o));
    float s = act ? (expf(acc0 - m) + expf(acc1 - m)) : 0.f;
#pragma unroll
    for (int o = 16; o > 0; o >>= 1) s += __shfl_xor_sync(0xffffffffu, s, o);
    float lse = m + logf(s);
    if (act)
        *(float2*)(out + (size_t)w * DO + 2 * lane) = make_float2(acc0 - lse, acc1 - lse);
}

// -------- launch --------
extern "C" void kernel_launch(void* const* d_in, const int* in_sizes, int n_in,
                              void* d_out, int out_size) {
    const float* x  = (const float*)d_in[0];
    const void*  ei = d_in[1];
    const float* W1 = (const float*)d_in[2];
    const float* b1 = (const float*)d_in[3];
    const float* W2 = (const float*)d_in[4];
    const float* b2 = (const float*)d_in[5];
    float* out = (float*)d_out;

    (void)in_sizes; (void)n_in; (void)out_size;

    k_gemm1_deg<<<GEMM1_BLOCKS + EDGE_BLOCKS, 256>>>(x, W1, ei);           // 0 (overlapped)
    k_scan<<<SCAN_NB, SCAN_BLK>>>();                                       // 1
    k_scatter<<<EDGE_BLOCKS, 256>>>(ei);                                   // 2
    k_agg1<<<(int)(((size_t)NN * 32 + 255) / 256), 256>>>(b1);             // 3  <- ncu capture slot
    k_gemm2<<<(NN + 127) / 128, 256>>>(W2);                                // 4
    k_agg2_logsm<<<(int)(((size_t)NN * 32 + 255) / 256), 256>>>(out, b2);  // 5
}